// round 3
// baseline (speedup 1.0000x reference)
#include <cuda_runtime.h>
#include <cuda_bf16.h>

#define BB 512
#define TT 512
#define LL 64

__device__ float g_res[BB];        // per-batch (normalizer - path_score)

#define FMA_F32X2(d, a, b, c) \
    asm("fma.rn.f32x2 %0, %1, %2, %3;" : "=l"(d) : "l"(a), "l"(b), "l"(c))
#define PACK_F32X2(out, lo, hi) \
    asm("mov.b64 %0, {%1, %2};" : "=l"(out) : "f"(lo), "f"(hi))
#define UNPACK_F32X2(lo, hi, in) \
    asm("mov.b64 {%0, %1}, %2;" : "=f"(lo), "=f"(hi) : "l"(in))

__global__ void __launch_bounds__(64) crf_main_kernel(
    const float* __restrict__ emission,   // [B,T,L]
    const int*   __restrict__ target,     // [B,T]
    const float* __restrict__ mask,       // [B,T]
    const float* __restrict__ start_trans,// [L]
    const float* __restrict__ trans,      // [L,L]
    const float* __restrict__ end_trans)  // [L]
{
    __shared__ float sm_m[TT + 1];
    __shared__ float sm_e[TT];
    __shared__ __align__(16) float sm_p[2][LL];
    __shared__ float sm_s0[2];
    __shared__ float sm_red[2];
    __shared__ float sm_x[2];

    const int b    = blockIdx.x;
    const int j    = threadIdx.x;      // label index 0..63
    const int warp = j >> 5;
    const int lane = j & 31;

    const float* emb = emission + (size_t)b * TT * LL;
    const int*   tgt = target   + (size_t)b * TT;

    // stage mask row into shared
    for (int t = j; t < TT; t += 64) sm_m[t] = mask[(size_t)b * TT + t];
    if (j == 0) sm_m[TT] = 0.0f;

    // E column j packed as f32x2 pairs over rows: Ecol2[i] = (E[2i][j], E[2i+1][j])
    unsigned long long Ecol2[LL / 2];
    #pragma unroll
    for (int i = 0; i < LL / 2; i++) {
        float e0 = __expf(trans[(2 * i)     * LL + j]);
        float e1 = __expf(trans[(2 * i + 1) * LL + j]);
        PACK_F32X2(Ecol2[i], e0, e1);
    }
    __syncthreads();

    // end-mask per timestep (block-uniform scalars)
    for (int t = j; t < TT; t += 64)
        sm_e[t] = (sm_m[t] > sm_m[t + 1]) ? 1.0f : 0.0f;
    __syncthreads();

    // ---------------- path score: parallel reduction over t ----------------
    float pacc = 0.0f;
    for (int t = 1 + j; t < TT; t += 64) {
        int   tp = tgt[t - 1];
        int   tc = tgt[t];
        pacc += sm_m[t] * (trans[tp * LL + tc] + emb[(size_t)t * LL + tc])
              + sm_e[t] * end_trans[tc];
    }
    if (j == 0) {
        int t0 = tgt[0];
        pacc += start_trans[t0] + emb[t0];
    }
    #pragma unroll
    for (int o = 16; o; o >>= 1) pacc += __shfl_xor_sync(0xffffffffu, pacc, o);
    if (lane == 0) sm_x[warp] = pacc;
    __syncthreads();
    const float path_score = sm_x[0] + sm_x[1];

    // ---------------- forward recursion (normalizer) ----------------
    const float et = end_trans[j];
    float s = start_trans[j] + emb[j];          // t = 0

    if (j == 0) sm_s0[1] = s;                   // initial block-uniform shift
    __syncthreads();
    float S = sm_s0[1];

    // emission prefetch, distance 2
    float em1 = emb[1 * LL + j];
    float em2 = emb[2 * LL + j];

    for (int t = 1; t < TT; t++) {
        const int buf = t & 1;
        const float em_cur = em1;
        em1 = em2;
        if (t + 2 < TT) em2 = emb[(size_t)(t + 2) * LL + j];

        // stabilized probs with block-uniform lagged shift S
        sm_p[buf][j] = __expf(s - S);
        if (j == 0) sm_s0[buf] = s;   // becomes next iteration's shift
        __syncthreads();

        // dot_j = sum_i p_i * E[i][j]  via packed f32x2 FMAs
        const ulonglong2* p4 = (const ulonglong2*)sm_p[buf];
        unsigned long long a0 = 0ull, a1 = 0ull, a2 = 0ull, a3 = 0ull;
        #pragma unroll
        for (int i = 0; i < LL / 8; i++) {        // 8 iters, 4 packed FMAs each
            const ulonglong2 vA = p4[2 * i];
            const ulonglong2 vB = p4[2 * i + 1];
            FMA_F32X2(a0, vA.x, Ecol2[4 * i + 0], a0);
            FMA_F32X2(a1, vA.y, Ecol2[4 * i + 1], a1);
            FMA_F32X2(a2, vB.x, Ecol2[4 * i + 2], a2);
            FMA_F32X2(a3, vB.y, Ecol2[4 * i + 3], a3);
        }
        float l0, h0, l1, h1, l2, h2, l3, h3;
        UNPACK_F32X2(l0, h0, a0);
        UNPACK_F32X2(l1, h1, a1);
        UNPACK_F32X2(l2, h2, a2);
        UNPACK_F32X2(l3, h3, a3);
        const float dot = ((l0 + h0) + (l1 + h1)) + ((l2 + h2) + (l3 + h3));

        const float nxt = S + __logf(dot) + em_cur;
        const float m   = sm_m[t];
        s = m * nxt + (1.0f - m) * s + sm_e[t] * et;

        S = sm_s0[buf];               // lag-1 shift for next iteration
    }

    // normalizer = logsumexp_j(s)  (exact max; runs once)
    float wm = s;
    #pragma unroll
    for (int o = 16; o; o >>= 1) wm = fmaxf(wm, __shfl_xor_sync(0xffffffffu, wm, o));
    if (lane == 0) sm_red[warp] = wm;
    __syncthreads();
    const float M = fmaxf(sm_red[0], sm_red[1]);
    float pe = __expf(s - M);
    #pragma unroll
    for (int o = 16; o; o >>= 1) pe += __shfl_xor_sync(0xffffffffu, pe, o);
    if (lane == 0) sm_x[warp] = pe;
    __syncthreads();
    if (j == 0) {
        const float norm = M + __logf(sm_x[0] + sm_x[1]);
        g_res[b] = norm - path_score;
    }
}

// deterministic mean over the 512 per-batch results
__global__ void crf_reduce_kernel(float* __restrict__ out) {
    __shared__ float sm[512];
    int t = threadIdx.x;
    sm[t] = g_res[t];
    __syncthreads();
    #pragma unroll
    for (int stride = 256; stride > 0; stride >>= 1) {
        if (t < stride) sm[t] += sm[t + stride];
        __syncthreads();
    }
    if (t == 0) out[0] = sm[0] * (1.0f / BB);
}

extern "C" void kernel_launch(void* const* d_in, const int* in_sizes, int n_in,
                              void* d_out, int out_size) {
    const float* emission    = (const float*)d_in[0];
    const int*   target      = (const int*)  d_in[1];
    const float* mask        = (const float*)d_in[2];
    const float* start_trans = (const float*)d_in[3];
    const float* trans       = (const float*)d_in[4];
    const float* end_trans   = (const float*)d_in[5];
    float* out = (float*)d_out;

    crf_main_kernel<<<BB, 64>>>(emission, target, mask, start_trans, trans, end_trans);
    crf_reduce_kernel<<<1, 512>>>(out);
}